// round 1
// baseline (speedup 1.0000x reference)
#include <cuda_runtime.h>
#include <math.h>

#define B_   4
#define L_   1024
#define H_   8
#define D_   512
#define DK_  64
#define HB_  32        // H*B
#define BL_  4096      // B*L

// ---------------- scratch (no allocations allowed) ----------------
__device__ float g_Sh[H_ * BL_];        // sigma projection, [h][b][l]
__device__ float g_Qp[BL_ * D_];        // Q @ Wq^T, [b*L+l][D]
__device__ float g_Kp[BL_ * D_];
__device__ float g_Vp[BL_ * D_];
__device__ float g_Op[BL_ * D_];        // attention out pre-Wo

// ---------------- sigma projection ----------------
__global__ void sigma_proj(const float* __restrict__ Sigma,
                           const float* __restrict__ Wsig) {
    int idx = blockIdx.x * blockDim.x + threadIdx.x;   // h*4096 + (b*L+l)
    if (idx >= H_ * BL_) return;
    int h  = idx >> 12;
    int bl = idx & 4095;
    const float* s = Sigma + (size_t)bl * H_;
    const float* w = Wsig + h * H_;
    float acc = 0.f;
#pragma unroll
    for (int j = 0; j < H_; ++j) acc += s[j] * w[j];
    g_Sh[idx] = acc;
}

// ---------------- Gaussian prior ----------------
// prior[g][m] = exp(-(l-m)^2 / (2 sigma^2)) / sum_m(...)
// (the 1/(sqrt(2pi)*sigma) factor cancels in the normalization, incl. sign)
__global__ __launch_bounds__(256) void prior_kernel(float* __restrict__ prior) {
    int g = blockIdx.x;                 // (h*B+b)*L + l  == Sh index
    int l = g & (L_ - 1);
    float sig  = g_Sh[g];
    float inv2 = 1.f / (2.f * sig * sig);
    int t = threadIdx.x;
    float e[4];
    float part = 0.f;
#pragma unroll
    for (int i = 0; i < 4; ++i) {
        int m = t + 256 * i;
        float d = (float)(l - m);
        e[i] = __expf(-d * d * inv2);
        part += e[i];
    }
#pragma unroll
    for (int o = 16; o > 0; o >>= 1) part += __shfl_xor_sync(0xffffffffu, part, o);
    __shared__ float red[8];
    if ((t & 31) == 0) red[t >> 5] = part;
    __syncthreads();
    if (t < 32) {
        float v = (t < 8) ? red[t] : 0.f;
#pragma unroll
        for (int o = 4; o > 0; o >>= 1) v += __shfl_xor_sync(0xffffffffu, v, o);
        if (t == 0) red[0] = v;
    }
    __syncthreads();
    float rinv = 1.f / red[0];
    float* outp = prior + (size_t)g * L_;
#pragma unroll
    for (int i = 0; i < 4; ++i) outp[t + 256 * i] = e[i] * rinv;
}

// ---------------- SGEMM: C[M,N] = A[M,K] @ W[N,K]^T ----------------
// M%128==0, N%128==0, K%8==0. 128x128 tile, 8x8 per thread, 256 threads.
__global__ __launch_bounds__(256) void sgemm_nt(const float* __restrict__ A,
                                                const float* __restrict__ W,
                                                float* __restrict__ C,
                                                int M, int N, int K) {
    __shared__ float As[8][128];
    __shared__ float Bs[8][128];
    int tid = threadIdx.x;
    int m0 = blockIdx.y * 128;
    int n0 = blockIdx.x * 128;
    int tx = tid & 15, ty = tid >> 4;
    int lr = tid >> 1;              // 0..127
    int lk = (tid & 1) * 4;         // 0 or 4

    float acc[8][8];
#pragma unroll
    for (int i = 0; i < 8; ++i)
#pragma unroll
        for (int j = 0; j < 8; ++j) acc[i][j] = 0.f;

    for (int kt = 0; kt < K; kt += 8) {
        float4 av = *(const float4*)(A + (size_t)(m0 + lr) * K + kt + lk);
        float4 bv = *(const float4*)(W + (size_t)(n0 + lr) * K + kt + lk);
        __syncthreads();
        As[lk + 0][lr] = av.x; As[lk + 1][lr] = av.y;
        As[lk + 2][lr] = av.z; As[lk + 3][lr] = av.w;
        Bs[lk + 0][lr] = bv.x; Bs[lk + 1][lr] = bv.y;
        Bs[lk + 2][lr] = bv.z; Bs[lk + 3][lr] = bv.w;
        __syncthreads();
#pragma unroll
        for (int kk = 0; kk < 8; ++kk) {
            float a[8], b[8];
            float4 t0 = *(const float4*)&As[kk][ty * 4];
            float4 t1 = *(const float4*)&As[kk][64 + ty * 4];
            a[0] = t0.x; a[1] = t0.y; a[2] = t0.z; a[3] = t0.w;
            a[4] = t1.x; a[5] = t1.y; a[6] = t1.z; a[7] = t1.w;
            float4 u0 = *(const float4*)&Bs[kk][tx * 4];
            float4 u1 = *(const float4*)&Bs[kk][64 + tx * 4];
            b[0] = u0.x; b[1] = u0.y; b[2] = u0.z; b[3] = u0.w;
            b[4] = u1.x; b[5] = u1.y; b[6] = u1.z; b[7] = u1.w;
#pragma unroll
            for (int i = 0; i < 8; ++i)
#pragma unroll
                for (int j = 0; j < 8; ++j) acc[i][j] += a[i] * b[j];
        }
    }
#pragma unroll
    for (int i = 0; i < 8; ++i) {
        int row = m0 + ((i < 4) ? (ty * 4 + i) : (64 + ty * 4 + i - 4));
        float* cp = C + (size_t)row * N + n0;
        *(float4*)(cp + tx * 4)      = make_float4(acc[i][0], acc[i][1], acc[i][2], acc[i][3]);
        *(float4*)(cp + 64 + tx * 4) = make_float4(acc[i][4], acc[i][5], acc[i][6], acc[i][7]);
    }
}

// ---------------- fused attention ----------------
// Block: 256 threads, 32 query rows of one (h,b).
// smem: Qs[32*64] | Kchunk (stride 65 for QK^T, stride 68 for V) | Ps[32*1025]
#define TM_   32
#define KC_   128
#define KS_STRIDE_K 65     // odd -> conflict-free lane-varying-row scalar LDS
#define KS_STRIDE_V 68     // 272B, 16B aligned -> legal broadcast float4 LDS
#define SM_QS   (TM_ * 64)                       // 2048
#define SM_KS   (KC_ * KS_STRIDE_V)              // 8704 (covers both strides)
#define SM_PS   (TM_ * 1025)                     // 32800
#define SMEM_FLOATS (SM_QS + SM_KS + SM_PS)      // 43552
#define SMEM_BYTES  (SMEM_FLOATS * 4)            // 174208

__global__ __launch_bounds__(256) void attn_kernel(float* __restrict__ series) {
    extern __shared__ float sm[];
    float* Qs = sm;
    float* Ks = sm + SM_QS;
    float* Ps = sm + SM_QS + SM_KS;

    int tid  = threadIdx.x;
    int hb   = blockIdx.y;          // h*B + b
    int h    = hb >> 2;
    int b    = hb & 3;
    int row0 = blockIdx.x * TM_;

    const float* Qbase = g_Qp + (size_t)(b * L_) * D_ + h * DK_;
    const float* Kbase = g_Kp + (size_t)(b * L_) * D_ + h * DK_;
    const float* Vbase = g_Vp + (size_t)(b * L_) * D_ + h * DK_;

    // phase 1: load 32 Q rows (512 float4)
#pragma unroll
    for (int i = 0; i < 2; ++i) {
        int q  = tid + 256 * i;
        int r  = q >> 4;
        int c4 = (q & 15) * 4;
        float4 v = *(const float4*)(Qbase + (size_t)(row0 + r) * D_ + c4);
        float* dst = Qs + r * 64 + c4;
        dst[0] = v.x; dst[1] = v.y; dst[2] = v.z; dst[3] = v.w;
    }

    int w   = tid >> 5;   // warp 0..7 -> rows w*4..w*4+3
    int lam = tid & 31;

    // phase 2: scores -> Ps (scaled by 1/sqrt(64))
    for (int c = 0; c < L_ / KC_; ++c) {
        __syncthreads();
#pragma unroll
        for (int i = 0; i < 8; ++i) {           // 2048 float4 loads
            int q  = tid + 256 * i;
            int kk = q >> 4;
            int c4 = (q & 15) * 4;
            float4 v = *(const float4*)(Kbase + (size_t)(c * KC_ + kk) * D_ + c4);
            float* dst = Ks + kk * KS_STRIDE_K + c4;
            dst[0] = v.x; dst[1] = v.y; dst[2] = v.z; dst[3] = v.w;
        }
        __syncthreads();
        float acc[4][4];
#pragma unroll
        for (int i = 0; i < 4; ++i)
#pragma unroll
            for (int j = 0; j < 4; ++j) acc[i][j] = 0.f;
#pragma unroll 8
        for (int d = 0; d < DK_; ++d) {
            float qv[4], kv[4];
#pragma unroll
            for (int i = 0; i < 4; ++i) qv[i] = Qs[(w * 4 + i) * 64 + d];
#pragma unroll
            for (int j = 0; j < 4; ++j) kv[j] = Ks[(lam + 32 * j) * KS_STRIDE_K + d];
#pragma unroll
            for (int i = 0; i < 4; ++i)
#pragma unroll
                for (int j = 0; j < 4; ++j) acc[i][j] += qv[i] * kv[j];
        }
#pragma unroll
        for (int i = 0; i < 4; ++i)
#pragma unroll
            for (int j = 0; j < 4; ++j)
                Ps[(w * 4 + i) * 1025 + c * KC_ + lam + 32 * j] = acc[i][j] * 0.125f;
    }
    __syncthreads();

    // phase 3: per-row softmax, write normalized probs to Ps and global series
    size_t srow0 = ((size_t)hb * L_ + row0) * L_;
#pragma unroll 1
    for (int i = 0; i < 4; ++i) {
        int r = w * 4 + i;
        float s[32];
#pragma unroll
        for (int j = 0; j < 32; ++j) s[j] = Ps[r * 1025 + lam + 32 * j];
        float mx = s[0];
#pragma unroll
        for (int j = 1; j < 32; ++j) mx = fmaxf(mx, s[j]);
#pragma unroll
        for (int o = 16; o > 0; o >>= 1) mx = fmaxf(mx, __shfl_xor_sync(0xffffffffu, mx, o));
        float sum = 0.f;
#pragma unroll
        for (int j = 0; j < 32; ++j) { s[j] = __expf(s[j] - mx); sum += s[j]; }
#pragma unroll
        for (int o = 16; o > 0; o >>= 1) sum += __shfl_xor_sync(0xffffffffu, sum, o);
        float inv = 1.f / sum;
        float* gdst = series + srow0 + (size_t)r * L_;
#pragma unroll
        for (int j = 0; j < 32; ++j) {
            float p = s[j] * inv;
            Ps[r * 1025 + lam + 32 * j] = p;
            gdst[lam + 32 * j] = p;
        }
    }

    // phase 4: out[r][d] = sum_m P[r][m] * V[m][d]
    int dg = tid & 7;     // d group: cols dg*8 .. dg*8+7
    int r4 = tid >> 3;    // row 0..31
    float oa[8];
#pragma unroll
    for (int j = 0; j < 8; ++j) oa[j] = 0.f;
    for (int c = 0; c < L_ / KC_; ++c) {
        __syncthreads();
#pragma unroll
        for (int i = 0; i < 8; ++i) {           // V chunk, stride 68
            int q  = tid + 256 * i;
            int kk = q >> 4;
            int c4 = (q & 15) * 4;
            float4 v = *(const float4*)(Vbase + (size_t)(c * KC_ + kk) * D_ + c4);
            float* dst = Ks + kk * KS_STRIDE_V + c4;
            dst[0] = v.x; dst[1] = v.y; dst[2] = v.z; dst[3] = v.w;
        }
        __syncthreads();
#pragma unroll 4
        for (int m = 0; m < KC_; ++m) {
            float p = Ps[r4 * 1025 + c * KC_ + m];
            float4 v0 = *(const float4*)(Ks + m * KS_STRIDE_V + dg * 8);
            float4 v1 = *(const float4*)(Ks + m * KS_STRIDE_V + dg * 8 + 4);
            oa[0] += p * v0.x; oa[1] += p * v0.y; oa[2] += p * v0.z; oa[3] += p * v0.w;
            oa[4] += p * v1.x; oa[5] += p * v1.y; oa[6] += p * v1.z; oa[7] += p * v1.w;
        }
    }
    float* od = g_Op + (size_t)(b * L_ + row0 + r4) * D_ + h * DK_ + dg * 8;
    *(float4*)od       = make_float4(oa[0], oa[1], oa[2], oa[3]);
    *(float4*)(od + 4) = make_float4(oa[4], oa[5], oa[6], oa[7]);
}

// ---------------- launch ----------------
extern "C" void kernel_launch(void* const* d_in, const int* in_sizes, int n_in,
                              void* d_out, int out_size) {
    (void)in_sizes; (void)n_in; (void)out_size;
    const float* Sigma = (const float*)d_in[0];
    const float* Q     = (const float*)d_in[1];
    const float* K     = (const float*)d_in[2];
    const float* V     = (const float*)d_in[3];
    const float* Wsig  = (const float*)d_in[4];
    const float* Wq    = (const float*)d_in[5];
    const float* Wk    = (const float*)d_in[6];
    const float* Wv    = (const float*)d_in[7];
    const float* Wo    = (const float*)d_in[8];

    float* outp   = (float*)d_out;
    float* prior  = outp;
    float* series = outp + (size_t)HB_ * L_ * L_;
    float* fout   = series + (size_t)HB_ * L_ * L_;

    float *pQp, *pKp, *pVp, *pOp;
    cudaGetSymbolAddress((void**)&pQp, g_Qp);
    cudaGetSymbolAddress((void**)&pKp, g_Kp);
    cudaGetSymbolAddress((void**)&pVp, g_Vp);
    cudaGetSymbolAddress((void**)&pOp, g_Op);

    cudaFuncSetAttribute(attn_kernel,
                         cudaFuncAttributeMaxDynamicSharedMemorySize, SMEM_BYTES);

    sigma_proj<<<(H_ * BL_ + 255) / 256, 256>>>(Sigma, Wsig);
    prior_kernel<<<H_ * BL_, 256>>>(prior);

    dim3 gproj(D_ / 128, BL_ / 128);   // (4, 32)
    sgemm_nt<<<gproj, 256>>>(Q, Wq, pQp, BL_, D_, D_);
    sgemm_nt<<<gproj, 256>>>(K, Wk, pKp, BL_, D_, D_);
    sgemm_nt<<<gproj, 256>>>(V, Wv, pVp, BL_, D_, D_);

    attn_kernel<<<dim3(L_ / TM_, HB_), 256, SMEM_BYTES>>>(series);

    sgemm_nt<<<gproj, 256>>>(pOp, Wo, fout, BL_, D_, D_);
}

// round 2
// speedup vs baseline: 3.1087x; 3.1087x over previous
#include <cuda_runtime.h>
#include <math.h>

#define B_   4
#define L_   1024
#define H_   8
#define D_   512
#define DK_  64
#define HB_  32        // H*B
#define BL_  4096      // B*L

// ---------------- scratch (no allocations allowed) ----------------
__device__ float g_Sh[H_ * BL_];
__device__ float g_Qp[BL_ * D_];
__device__ float g_Kp[BL_ * D_];
__device__ float g_Vp[BL_ * D_];
__device__ float g_Op[BL_ * D_];

// ---------------- helpers ----------------
__device__ __forceinline__ unsigned f2tf(float x) {
    unsigned r; asm("cvt.rna.tf32.f32 %0, %1;" : "=r"(r) : "f"(x)); return r;
}
// D += A(16x8) * B(8x8), tf32 in, fp32 acc
__device__ __forceinline__ void mma8(float* c, const unsigned* a, const unsigned* b) {
    asm volatile("mma.sync.aligned.m16n8k8.row.col.f32.tf32.tf32.f32 "
        "{%0,%1,%2,%3}, {%4,%5,%6,%7}, {%8,%9}, {%0,%1,%2,%3};"
        : "+f"(c[0]), "+f"(c[1]), "+f"(c[2]), "+f"(c[3])
        : "r"(a[0]), "r"(a[1]), "r"(a[2]), "r"(a[3]), "r"(b[0]), "r"(b[1]));
}
__device__ __forceinline__ void cp16(float* dst, const float* src) {
    unsigned d = (unsigned)__cvta_generic_to_shared(dst);
    asm volatile("cp.async.cg.shared.global [%0], [%1], 16;" :: "r"(d), "l"(src));
}

// ---------------- sigma projection ----------------
__global__ void sigma_proj(const float* __restrict__ Sigma,
                           const float* __restrict__ Wsig) {
    int idx = blockIdx.x * blockDim.x + threadIdx.x;
    if (idx >= H_ * BL_) return;
    int h  = idx >> 12;
    int bl = idx & 4095;
    const float* s = Sigma + (size_t)bl * H_;
    const float* w = Wsig + h * H_;
    float acc = 0.f;
#pragma unroll
    for (int j = 0; j < H_; ++j) acc += s[j] * w[j];
    g_Sh[idx] = acc;
}

// ---------------- Gaussian prior ----------------
__global__ __launch_bounds__(256) void prior_kernel(float* __restrict__ prior) {
    int g = blockIdx.x;
    int l = g & (L_ - 1);
    float sig  = g_Sh[g];
    float inv2 = 1.f / (2.f * sig * sig);
    int t = threadIdx.x;
    float e[4];
    float part = 0.f;
#pragma unroll
    for (int i = 0; i < 4; ++i) {
        int m = t + 256 * i;
        float d = (float)(l - m);
        e[i] = __expf(-d * d * inv2);
        part += e[i];
    }
#pragma unroll
    for (int o = 16; o > 0; o >>= 1) part += __shfl_xor_sync(0xffffffffu, part, o);
    __shared__ float red[8];
    if ((t & 31) == 0) red[t >> 5] = part;
    __syncthreads();
    if (t < 32) {
        float v = (t < 8) ? red[t] : 0.f;
#pragma unroll
        for (int o = 4; o > 0; o >>= 1) v += __shfl_xor_sync(0xffffffffu, v, o);
        if (t == 0) red[0] = v;
    }
    __syncthreads();
    float rinv = 1.f / red[0];
    float* outp = prior + (size_t)g * L_;
#pragma unroll
    for (int i = 0; i < 4; ++i) outp[t + 256 * i] = e[i] * rinv;
}

// ---------------- tf32 GEMM: C[4096,512] = A[4096,512] @ W[512,512]^T ----------------
// 128x128 block tile, kc=32 double buffered via cp.async, 8 warps, warp tile 64x32.
#define GST 36                                   // smem row stride (36%32==4 -> frag loads conflict-free)
#define GEMM_SMEM_FLOATS (4 * 128 * GST)         // 2 bufs x (A,W) x 128x36
#define GEMM_SMEM_BYTES  (GEMM_SMEM_FLOATS * 4)  // 73728

__global__ __launch_bounds__(256) void gemm_tf32(const float* __restrict__ A,
                                                 const float* __restrict__ W,
                                                 float* __restrict__ C) {
    extern __shared__ float sm[];
    float* Asm[2] = { sm,                sm + 128 * GST };
    float* Wsm[2] = { sm + 2 * 128 * GST, sm + 3 * 128 * GST };

    const int K = 512, N = 512;
    int tid  = threadIdx.x;
    int lane = tid & 31, w = tid >> 5;
    int gid  = lane >> 2, tig = lane & 3;
    int wm   = (w & 1) * 64;        // warp m offset
    int wn   = (w >> 1) * 32;       // warp n offset
    int m0   = blockIdx.y * 128;
    int n0   = blockIdx.x * 128;

    int lr = tid >> 3;              // loader row 0..31
    int lk = (tid & 7) * 4;         // loader k 0,4,..,28

    const float* Ag = A + (size_t)m0 * K;
    const float* Wg = W + (size_t)n0 * K;

    float acc[4][4][4];
#pragma unroll
    for (int i = 0; i < 4; ++i)
#pragma unroll
        for (int j = 0; j < 4; ++j)
#pragma unroll
            for (int q = 0; q < 4; ++q) acc[i][j][q] = 0.f;

    // prefetch first chunk
#pragma unroll
    for (int i = 0; i < 4; ++i) {
        int r = lr + 32 * i;
        cp16(&Asm[0][r * GST + lk], Ag + (size_t)r * K + lk);
        cp16(&Wsm[0][r * GST + lk], Wg + (size_t)r * K + lk);
    }
    asm volatile("cp.async.commit_group;");

    int cur = 0;
    for (int kt = 0; kt < K; kt += 32) {
        if (kt + 32 < K) {
#pragma unroll
            for (int i = 0; i < 4; ++i) {
                int r = lr + 32 * i;
                cp16(&Asm[cur ^ 1][r * GST + lk], Ag + (size_t)r * K + kt + 32 + lk);
                cp16(&Wsm[cur ^ 1][r * GST + lk], Wg + (size_t)r * K + kt + 32 + lk);
            }
            asm volatile("cp.async.commit_group;");
            asm volatile("cp.async.wait_group 1;");
        } else {
            asm volatile("cp.async.wait_group 0;");
        }
        __syncthreads();

        const float* Ab = Asm[cur];
        const float* Wb = Wsm[cur];
#pragma unroll
        for (int ks = 0; ks < 4; ++ks) {
            int k0 = ks * 8;
            unsigned af[4][4], bf[4][2];
#pragma unroll
            for (int i = 0; i < 4; ++i) {
                int r = wm + i * 16;
                af[i][0] = f2tf(Ab[(r + gid) * GST + k0 + tig]);
                af[i][1] = f2tf(Ab[(r + gid + 8) * GST + k0 + tig]);
                af[i][2] = f2tf(Ab[(r + gid) * GST + k0 + tig + 4]);
                af[i][3] = f2tf(Ab[(r + gid + 8) * GST + k0 + tig + 4]);
            }
#pragma unroll
            for (int j = 0; j < 4; ++j) {
                int nrow = wn + j * 8 + gid;
                bf[j][0] = f2tf(Wb[nrow * GST + k0 + tig]);
                bf[j][1] = f2tf(Wb[nrow * GST + k0 + tig + 4]);
            }
#pragma unroll
            for (int i = 0; i < 4; ++i)
#pragma unroll
                for (int j = 0; j < 4; ++j) mma8(acc[i][j], af[i], bf[j]);
        }
        __syncthreads();
        cur ^= 1;
    }

    // epilogue
#pragma unroll
    for (int i = 0; i < 4; ++i) {
        int r = m0 + wm + i * 16 + gid;
#pragma unroll
        for (int j = 0; j < 4; ++j) {
            int cc = n0 + wn + j * 8 + tig * 2;
            float* p0 = C + (size_t)r * N + cc;
            *(float2*)p0 = make_float2(acc[i][j][0], acc[i][j][1]);
            float* p1 = C + (size_t)(r + 8) * N + cc;
            *(float2*)p1 = make_float2(acc[i][j][2], acc[i][j][3]);
        }
    }
}

// ---------------- fused attention with tf32 mma ----------------
// Block: 256 thr (8 warps), 32 query rows of one (h,b). Chunks of 256 keys.
#define TM_   32
#define KC_   256
#define QSTR  68     // 68%32==4 -> A-frag loads conflict-free
#define KSTR  68     // K chunk [key][d], gid on key row -> conflict-free
#define VSTR  72     // V chunk [key][d], tig on key row (72%32==8) -> conflict-free
#define PSST  1028   // Ps stride (1028%32==4)
#define SM_QS (TM_ * QSTR)          // 2176
#define SM_KV (KC_ * VSTR)          // 18432 (covers both strides)
#define SM_PS (TM_ * PSST)          // 32896
#define ATTN_SMEM_BYTES ((SM_QS + SM_KV + SM_PS) * 4)   // 214016

__global__ __launch_bounds__(256) void attn_mma(float* __restrict__ series) {
    extern __shared__ float sm[];
    float* Qs  = sm;
    float* KVs = sm + SM_QS;
    float* Ps  = sm + SM_QS + SM_KV;

    int tid  = threadIdx.x;
    int lane = tid & 31, w = tid >> 5;
    int gid  = lane >> 2, tig = lane & 3;
    int hb   = blockIdx.y;
    int h    = hb >> 2;
    int b    = hb & 3;
    int row0 = blockIdx.x * TM_;

    const float* Qbase = g_Qp + (size_t)(b * L_) * D_ + h * DK_;
    const float* Kbase = g_Kp + (size_t)(b * L_) * D_ + h * DK_;
    const float* Vbase = g_Vp + (size_t)(b * L_) * D_ + h * DK_;

    // load Q tile (32x64)
#pragma unroll
    for (int i = 0; i < 2; ++i) {
        int q  = tid + 256 * i;
        int r  = q >> 4;
        int c4 = (q & 15) * 4;
        float4 v = *(const float4*)(Qbase + (size_t)(row0 + r) * D_ + c4);
        *(float4*)(Qs + r * QSTR + c4) = v;
    }
    __syncthreads();

    // Q fragments for this warp's m-tile, pre-scaled by 1/sqrt(64)
    int mt = w & 1;
    unsigned qf[8][4];
#pragma unroll
    for (int ks = 0; ks < 8; ++ks) {
        int k0 = ks * 8, rb = mt * 16;
        qf[ks][0] = f2tf(0.125f * Qs[(rb + gid) * QSTR + k0 + tig]);
        qf[ks][1] = f2tf(0.125f * Qs[(rb + gid + 8) * QSTR + k0 + tig]);
        qf[ks][2] = f2tf(0.125f * Qs[(rb + gid) * QSTR + k0 + tig + 4]);
        qf[ks][3] = f2tf(0.125f * Qs[(rb + gid + 8) * QSTR + k0 + tig + 4]);
    }

    // ---- phase 2: scores = Q K^T / 8 -> Ps ----
    for (int c = 0; c < L_ / KC_; ++c) {
        __syncthreads();
#pragma unroll
        for (int i = 0; i < 16; ++i) {
            int q  = tid + 256 * i;
            int kk = q >> 4;
            int c4 = (q & 15) * 4;
            float4 v = *(const float4*)(Kbase + (size_t)(c * KC_ + kk) * D_ + c4);
            *(float4*)(KVs + kk * KSTR + c4) = v;
        }
        __syncthreads();

        int nt0 = (w >> 1) * 8;     // 8 n-tiles per warp
#pragma unroll
        for (int jt = 0; jt < 8; ++jt) {
            int n0 = (nt0 + jt) * 8;
            float acc[4] = {0.f, 0.f, 0.f, 0.f};
#pragma unroll
            for (int ks = 0; ks < 8; ++ks) {
                unsigned bf[2];
                const float* kb = KVs + (n0 + gid) * KSTR + ks * 8;
                bf[0] = f2tf(kb[tig]);
                bf[1] = f2tf(kb[tig + 4]);
                mma8(acc, qf[ks], bf);
            }
            int mrow = mt * 16 + gid;
            int cc   = c * KC_ + n0 + tig * 2;
            *(float2*)(Ps + mrow * PSST + cc)       = make_float2(acc[0], acc[1]);
            *(float2*)(Ps + (mrow + 8) * PSST + cc) = make_float2(acc[2], acc[3]);
        }
    }
    __syncthreads();

    // ---- phase 3: softmax rows, write Ps + series ----
    size_t srow0 = ((size_t)hb * L_ + row0) * L_;
#pragma unroll 1
    for (int i = 0; i < 4; ++i) {
        int r = w * 4 + i;
        float s[32];
#pragma unroll
        for (int j = 0; j < 32; ++j) s[j] = Ps[r * PSST + lane + 32 * j];
        float mx = s[0];
#pragma unroll
        for (int j = 1; j < 32; ++j) mx = fmaxf(mx, s[j]);
#pragma unroll
        for (int o = 16; o > 0; o >>= 1) mx = fmaxf(mx, __shfl_xor_sync(0xffffffffu, mx, o));
        float sum = 0.f;
#pragma unroll
        for (int j = 0; j < 32; ++j) { s[j] = __expf(s[j] - mx); sum += s[j]; }
#pragma unroll
        for (int o = 16; o > 0; o >>= 1) sum += __shfl_xor_sync(0xffffffffu, sum, o);
        float inv = 1.f / sum;
        float* gdst = series + srow0 + (size_t)r * L_;
#pragma unroll
        for (int j = 0; j < 32; ++j) {
            float p = s[j] * inv;
            Ps[r * PSST + lane + 32 * j] = p;
            gdst[lane + 32 * j] = p;
        }
    }

    // ---- phase 4: out = P V ----
    int nt0 = w >> 1;               // n-tiles nt0 and nt0+4
    float oacc[2][4];
#pragma unroll
    for (int t = 0; t < 2; ++t)
#pragma unroll
        for (int q = 0; q < 4; ++q) oacc[t][q] = 0.f;

    for (int c = 0; c < L_ / KC_; ++c) {
        __syncthreads();
#pragma unroll
        for (int i = 0; i < 16; ++i) {
            int q  = tid + 256 * i;
            int kk = q >> 4;
            int c4 = (q & 15) * 4;
            float4 v = *(const float4*)(Vbase + (size_t)(c * KC_ + kk) * D_ + c4);
            *(float4*)(KVs + kk * VSTR + c4) = v;
        }
        __syncthreads();

#pragma unroll 2
        for (int ks = 0; ks < KC_ / 8; ++ks) {
            int kloc = ks * 8;
            int kg   = c * KC_ + kloc;
            unsigned af[4], bf[2];
            af[0] = f2tf(Ps[(mt * 16 + gid) * PSST + kg + tig]);
            af[1] = f2tf(Ps[(mt * 16 + gid + 8) * PSST + kg + tig]);
            af[2] = f2tf(Ps[(mt * 16 + gid) * PSST + kg + tig + 4]);
            af[3] = f2tf(Ps[(mt * 16 + gid + 8) * PSST + kg + tig + 4]);

            const float* vb0 = KVs + (kloc + tig) * VSTR;
            const float* vb1 = KVs + (kloc + tig + 4) * VSTR;
            bf[0] = f2tf(vb0[nt0 * 8 + gid]);
            bf[1] = f2tf(vb1[nt0 * 8 + gid]);
            mma8(oacc[0], af, bf);
            bf[0] = f2tf(vb0[(nt0 + 4) * 8 + gid]);
            bf[1] = f2tf(vb1[(nt0 + 4) * 8 + gid]);
            mma8(oacc[1], af, bf);
        }
    }

    // epilogue -> g_Op
    int mrow = row0 + mt * 16 + gid;
#pragma unroll
    for (int t = 0; t < 2; ++t) {
        int nt = nt0 + 4 * t;
        float* od = g_Op + (size_t)(b * L_ + mrow) * D_ + h * DK_ + nt * 8 + tig * 2;
        *(float2*)od             = make_float2(oacc[t][0], oacc[t][1]);
        *(float2*)(od + 8 * D_)  = make_float2(oacc[t][2], oacc[t][3]);
    }
}

// ---------------- launch ----------------
extern "C" void kernel_launch(void* const* d_in, const int* in_sizes, int n_in,
                              void* d_out, int out_size) {
    (void)in_sizes; (void)n_in; (void)out_size;
    const float* Sigma = (const float*)d_in[0];
    const float* Q     = (const float*)d_in[1];
    const float* K     = (const float*)d_in[2];
    const float* V     = (const float*)d_in[3];
    const float* Wsig  = (const float*)d_in[4];
    const float* Wq    = (const float*)d_in[5];
    const float* Wk    = (const float*)d_in[6];
    const float* Wv    = (const float*)d_in[7];
    const float* Wo    = (const float*)d_in[8];

    float* outp   = (float*)d_out;
    float* prior  = outp;
    float* series = outp + (size_t)HB_ * L_ * L_;
    float* fout   = series + (size_t)HB_ * L_ * L_;

    float *pQp, *pKp, *pVp, *pOp;
    cudaGetSymbolAddress((void**)&pQp, g_Qp);
    cudaGetSymbolAddress((void**)&pKp, g_Kp);
    cudaGetSymbolAddress((void**)&pVp, g_Vp);
    cudaGetSymbolAddress((void**)&pOp, g_Op);

    cudaFuncSetAttribute(gemm_tf32,
                         cudaFuncAttributeMaxDynamicSharedMemorySize, GEMM_SMEM_BYTES);
    cudaFuncSetAttribute(attn_mma,
                         cudaFuncAttributeMaxDynamicSharedMemorySize, ATTN_SMEM_BYTES);

    sigma_proj<<<(H_ * BL_ + 255) / 256, 256>>>(Sigma, Wsig);
    prior_kernel<<<H_ * BL_, 256>>>(prior);

    dim3 gproj(D_ / 128, BL_ / 128);   // (4, 32)
    gemm_tf32<<<gproj, 256, GEMM_SMEM_BYTES>>>(Q, Wq, pQp);
    gemm_tf32<<<gproj, 256, GEMM_SMEM_BYTES>>>(K, Wk, pKp);
    gemm_tf32<<<gproj, 256, GEMM_SMEM_BYTES>>>(V, Wv, pVp);

    attn_mma<<<dim3(L_ / TM_, HB_), 256, ATTN_SMEM_BYTES>>>(series);

    gemm_tf32<<<gproj, 256, GEMM_SMEM_BYTES>>>(pOp, Wo, fout);
}

// round 4
// speedup vs baseline: 3.4052x; 1.0954x over previous
#include <cuda_runtime.h>
#include <math.h>

#define B_   4
#define L_   1024
#define H_   8
#define D_   512
#define DK_  64
#define HB_  32        // H*B
#define BL_  4096      // B*L

// ---------------- scratch (no allocations allowed) ----------------
__device__ float g_Sh[H_ * BL_];
__device__ float g_Qp[BL_ * D_];
__device__ float g_Kp[BL_ * D_];
__device__ float g_Vp[BL_ * D_];
__device__ float g_Op[BL_ * D_];

// ---------------- helpers ----------------
__device__ __forceinline__ unsigned f2tf(float x) {
    unsigned r; asm("cvt.rna.tf32.f32 %0, %1;" : "=r"(r) : "f"(x)); return r;
}
__device__ __forceinline__ void mma8(float* c, const unsigned* a, const unsigned* b) {
    asm volatile("mma.sync.aligned.m16n8k8.row.col.f32.tf32.tf32.f32 "
        "{%0,%1,%2,%3}, {%4,%5,%6,%7}, {%8,%9}, {%0,%1,%2,%3};"
        : "+f"(c[0]), "+f"(c[1]), "+f"(c[2]), "+f"(c[3])
        : "r"(a[0]), "r"(a[1]), "r"(a[2]), "r"(a[3]), "r"(b[0]), "r"(b[1]));
}
__device__ __forceinline__ void cp16(float* dst, const float* src) {
    unsigned d = (unsigned)__cvta_generic_to_shared(dst);
    asm volatile("cp.async.cg.shared.global [%0], [%1], 16;" :: "r"(d), "l"(src));
}

// ---------------- sigma projection ----------------
__global__ void sigma_proj(const float* __restrict__ Sigma,
                           const float* __restrict__ Wsig) {
    int idx = blockIdx.x * blockDim.x + threadIdx.x;
    if (idx >= H_ * BL_) return;
    int h  = idx >> 12;
    int bl = idx & 4095;
    const float* s = Sigma + (size_t)bl * H_;
    const float* w = Wsig + h * H_;
    float acc = 0.f;
#pragma unroll
    for (int j = 0; j < H_; ++j) acc += s[j] * w[j];
    g_Sh[idx] = acc;
}

// ---------------- Gaussian prior ----------------
__global__ __launch_bounds__(256) void prior_kernel(float* __restrict__ prior) {
    int g = blockIdx.x;
    int l = g & (L_ - 1);
    float sig  = g_Sh[g];
    float inv2 = 1.f / (2.f * sig * sig);
    int t = threadIdx.x;
    float e[4];
    float part = 0.f;
#pragma unroll
    for (int i = 0; i < 4; ++i) {
        int m = t + 256 * i;
        float d = (float)(l - m);
        e[i] = __expf(-d * d * inv2);
        part += e[i];
    }
#pragma unroll
    for (int o = 16; o > 0; o >>= 1) part += __shfl_xor_sync(0xffffffffu, part, o);
    __shared__ float red[8];
    if ((t & 31) == 0) red[t >> 5] = part;
    __syncthreads();
    if (t < 32) {
        float v = (t < 8) ? red[t] : 0.f;
#pragma unroll
        for (int o = 4; o > 0; o >>= 1) v += __shfl_xor_sync(0xffffffffu, v, o);
        if (t == 0) red[0] = v;
    }
    __syncthreads();
    float rinv = 1.f / red[0];
    float* outp = prior + (size_t)g * L_;
#pragma unroll
    for (int i = 0; i < 4; ++i) outp[t + 256 * i] = e[i] * rinv;
}

// ---------------- tf32 GEMM: C[4096,512] = A @ W^T, tile 64x128 ----------------
#define GST   36
#define G_ASZ (64 * GST)
#define G_WSZ (128 * GST)
#define GEMM_SMEM_BYTES ((G_ASZ + G_WSZ) * 2 * 4)   // 55296

__global__ __launch_bounds__(256) void gemm64(
        const float* __restrict__ A0, const float* __restrict__ W0, float* __restrict__ C0,
        const float* __restrict__ A1, const float* __restrict__ W1, float* __restrict__ C1,
        const float* __restrict__ A2, const float* __restrict__ W2, float* __restrict__ C2) {
    const float *A, *W; float *C;
    if (blockIdx.z == 0)      { A = A0; W = W0; C = C0; }
    else if (blockIdx.z == 1) { A = A1; W = W1; C = C1; }
    else                      { A = A2; W = W2; C = C2; }

    extern __shared__ float sm[];
    float* As[2] = { sm,                 sm + G_ASZ + G_WSZ };
    float* Ws[2] = { sm + G_ASZ,         sm + 2 * G_ASZ + G_WSZ };

    const int K = 512, N = 512;
    int tid = threadIdx.x, lane = tid & 31, w = tid >> 5;
    int gid = lane >> 2, tig = lane & 3;
    int mt = (w & 3) * 16, nh = (w >> 2) * 64;
    int m0 = blockIdx.y * 64, n0 = blockIdx.x * 128;

    float acc[8][4];
#pragma unroll
    for (int j = 0; j < 8; ++j)
#pragma unroll
        for (int q = 0; q < 4; ++q) acc[j][q] = 0.f;

    // prefetch chunk 0
#pragma unroll
    for (int j = 0; j < 2; ++j) {
        int i = tid + 256 * j, r = i >> 3, c4 = (i & 7) * 4;
        cp16(&As[0][r * GST + c4], A + (size_t)(m0 + r) * K + c4);
    }
#pragma unroll
    for (int j = 0; j < 4; ++j) {
        int i = tid + 256 * j, r = i >> 3, c4 = (i & 7) * 4;
        cp16(&Ws[0][r * GST + c4], W + (size_t)(n0 + r) * K + c4);
    }
    asm volatile("cp.async.commit_group;");

    int cur = 0;
    for (int kt = 0; kt < K; kt += 32) {
        if (kt + 32 < K) {
            int nb = cur ^ 1;
#pragma unroll
            for (int j = 0; j < 2; ++j) {
                int i = tid + 256 * j, r = i >> 3, c4 = (i & 7) * 4;
                cp16(&As[nb][r * GST + c4], A + (size_t)(m0 + r) * K + kt + 32 + c4);
            }
#pragma unroll
            for (int j = 0; j < 4; ++j) {
                int i = tid + 256 * j, r = i >> 3, c4 = (i & 7) * 4;
                cp16(&Ws[nb][r * GST + c4], W + (size_t)(n0 + r) * K + kt + 32 + c4);
            }
            asm volatile("cp.async.commit_group;");
            asm volatile("cp.async.wait_group 1;");
        } else {
            asm volatile("cp.async.wait_group 0;");
        }
        __syncthreads();

        const float* Ab = As[cur];
        const float* Wb = Ws[cur];
#pragma unroll
        for (int ks = 0; ks < 4; ++ks) {
            int k0 = ks * 8;
            unsigned af[4], bf[8][2];
            af[0] = f2tf(Ab[(mt + gid) * GST + k0 + tig]);
            af[1] = f2tf(Ab[(mt + gid + 8) * GST + k0 + tig]);
            af[2] = f2tf(Ab[(mt + gid) * GST + k0 + tig + 4]);
            af[3] = f2tf(Ab[(mt + gid + 8) * GST + k0 + tig + 4]);
#pragma unroll
            for (int j = 0; j < 8; ++j) {
                const float* wb = Wb + (nh + j * 8 + gid) * GST + k0;
                bf[j][0] = f2tf(wb[tig]);
                bf[j][1] = f2tf(wb[tig + 4]);
            }
#pragma unroll
            for (int j = 0; j < 8; ++j) mma8(acc[j], af, bf[j]);
        }
        __syncthreads();
        cur ^= 1;
    }

#pragma unroll
    for (int j = 0; j < 8; ++j) {
        int cc = n0 + nh + j * 8 + tig * 2;
        float* p0 = C + (size_t)(m0 + mt + gid) * N + cc;
        *(float2*)p0 = make_float2(acc[j][0], acc[j][1]);
        float* p1 = C + (size_t)(m0 + mt + gid + 8) * N + cc;
        *(float2*)p1 = make_float2(acc[j][2], acc[j][3]);
    }
}

// ---------------- fused 2-pass attention, TM=64 rows/block ----------------
#define TMR  64
#define CK   128
#define QSTR 68
#define KSTR 68
#define VSTR 72
#define PST  132
#define SM_PQ (TMR * PST)     // 8448 (P buffer, Q staged here first)
#define SM_K  (CK * KSTR)     // 8704
#define SM_V  (CK * VSTR)     // 9216
#define ATTN_SMEM ((SM_PQ + SM_K + SM_V) * 4)   // 105472

__global__ __launch_bounds__(256, 2) void attn2(float* __restrict__ series) {
    extern __shared__ float sm[];
    float* Ps = sm;
    float* Ks = sm + SM_PQ;
    float* Vs = Ks + SM_K;

    int tid = threadIdx.x, lane = tid & 31, w = tid >> 5;
    int gid = lane >> 2, tig = lane & 3;
    int mt = (w & 3) * 16;      // warp row base
    int ch = w >> 2;            // 0/1: score col half / d half
    int hb = blockIdx.y, h = hb >> 2, b = hb & 3;
    int row0 = blockIdx.x * TMR;

    const float* Qb = g_Qp + (size_t)(b * L_) * D_ + h * DK_;
    const float* Kb = g_Kp + (size_t)(b * L_) * D_ + h * DK_;
    const float* Vb = g_Vp + (size_t)(b * L_) * D_ + h * DK_;

    // stage Q (64x64) into Ps region, preload frags (pre-scaled by 1/8)
#pragma unroll
    for (int i = 0; i < 4; ++i) {
        int q = tid + 256 * i, r = q >> 4, c4 = (q & 15) * 4;
        *(float4*)(Ps + r * QSTR + c4) = *(const float4*)(Qb + (size_t)(row0 + r) * D_ + c4);
    }
    __syncthreads();
    unsigned qf[8][4];
#pragma unroll
    for (int ks = 0; ks < 8; ++ks) {
        int k0 = ks * 8;
        qf[ks][0] = f2tf(0.125f * Ps[(mt + gid) * QSTR + k0 + tig]);
        qf[ks][1] = f2tf(0.125f * Ps[(mt + gid + 8) * QSTR + k0 + tig]);
        qf[ks][2] = f2tf(0.125f * Ps[(mt + gid) * QSTR + k0 + tig + 4]);
        qf[ks][3] = f2tf(0.125f * Ps[(mt + gid + 8) * QSTR + k0 + tig + 4]);
    }

    float m[2] = { -1e30f, -1e30f }, z[2] = { 0.f, 0.f };

    // ---- pass 1: online row max / sum ----
    for (int c = 0; c < L_ / CK; ++c) {
        __syncthreads();
#pragma unroll
        for (int i = 0; i < 8; ++i) {
            int q = tid + 256 * i, r = q >> 4, c4 = (q & 15) * 4;
            *(float4*)(Ks + r * KSTR + c4) = *(const float4*)(Kb + (size_t)(c * CK + r) * D_ + c4);
        }
        __syncthreads();

        float s[8][4];
#pragma unroll
        for (int j = 0; j < 8; ++j) { s[j][0] = s[j][1] = s[j][2] = s[j][3] = 0.f; }
#pragma unroll
        for (int ks = 0; ks < 8; ++ks) {
            int k0 = ks * 8;
#pragma unroll
            for (int j = 0; j < 8; ++j) {
                unsigned bf[2];
                const float* kb = Ks + (ch * 64 + j * 8 + gid) * KSTR + k0;
                bf[0] = f2tf(kb[tig]);
                bf[1] = f2tf(kb[tig + 4]);
                mma8(s[j], qf[ks], bf);
            }
        }
        float cm0 = -1e30f, cm1 = -1e30f;
#pragma unroll
        for (int j = 0; j < 8; ++j) {
            cm0 = fmaxf(cm0, fmaxf(s[j][0], s[j][1]));
            cm1 = fmaxf(cm1, fmaxf(s[j][2], s[j][3]));
        }
        cm0 = fmaxf(cm0, __shfl_xor_sync(0xffffffffu, cm0, 1));
        cm0 = fmaxf(cm0, __shfl_xor_sync(0xffffffffu, cm0, 2));
        cm1 = fmaxf(cm1, __shfl_xor_sync(0xffffffffu, cm1, 1));
        cm1 = fmaxf(cm1, __shfl_xor_sync(0xffffffffu, cm1, 2));
        float nm0 = fmaxf(m[0], cm0), nm1 = fmaxf(m[1], cm1);
        float zl0 = 0.f, zl1 = 0.f;
#pragma unroll
        for (int j = 0; j < 8; ++j) {
            zl0 += __expf(s[j][0] - nm0) + __expf(s[j][1] - nm0);
            zl1 += __expf(s[j][2] - nm1) + __expf(s[j][3] - nm1);
        }
        zl0 += __shfl_xor_sync(0xffffffffu, zl0, 1);
        zl0 += __shfl_xor_sync(0xffffffffu, zl0, 2);
        zl1 += __shfl_xor_sync(0xffffffffu, zl1, 1);
        zl1 += __shfl_xor_sync(0xffffffffu, zl1, 2);
        z[0] = z[0] * __expf(m[0] - nm0) + zl0; m[0] = nm0;
        z[1] = z[1] * __expf(m[1] - nm1) + zl1; m[1] = nm1;
    }

    // merge the two column-halves' stats (Vs as scratch; unused so far)
    __syncthreads();
    if (tig == 0) {
        Vs[ch * 64 + mt + gid]           = m[0];
        Vs[ch * 64 + mt + gid + 8]       = m[1];
        Vs[128 + ch * 64 + mt + gid]     = z[0];
        Vs[128 + ch * 64 + mt + gid + 8] = z[1];
    }
    __syncthreads();
    float invz[2];
    {
        float ma = Vs[mt + gid],           mb = Vs[64 + mt + gid];
        float za = Vs[128 + mt + gid],     zb = Vs[192 + mt + gid];
        float M = fmaxf(ma, mb);
        m[0] = M; invz[0] = 1.f / (za * __expf(ma - M) + zb * __expf(mb - M));
        ma = Vs[mt + gid + 8];  mb = Vs[64 + mt + gid + 8];
        za = Vs[128 + mt + gid + 8]; zb = Vs[192 + mt + gid + 8];
        M = fmaxf(ma, mb);
        m[1] = M; invz[1] = 1.f / (za * __expf(ma - M) + zb * __expf(mb - M));
    }

    float oa[4][4];
#pragma unroll
    for (int j = 0; j < 4; ++j)
#pragma unroll
        for (int q = 0; q < 4; ++q) oa[j][q] = 0.f;

    size_t srow = ((size_t)hb * L_ + row0 + mt) * L_;

    // ---- pass 2: recompute scores, write series, fused PV ----
    for (int c = 0; c < L_ / CK; ++c) {
        __syncthreads();
#pragma unroll
        for (int i = 0; i < 8; ++i) {
            int q = tid + 256 * i, r = q >> 4, c4 = (q & 15) * 4;
            *(float4*)(Ks + r * KSTR + c4) = *(const float4*)(Kb + (size_t)(c * CK + r) * D_ + c4);
        }
#pragma unroll
        for (int i = 0; i < 8; ++i) {
            int q = tid + 256 * i, r = q >> 4, c4 = (q & 15) * 4;
            *(float4*)(Vs + r * VSTR + c4) = *(const float4*)(Vb + (size_t)(c * CK + r) * D_ + c4);
        }
        __syncthreads();

        float s[8][4];
#pragma unroll
        for (int j = 0; j < 8; ++j) { s[j][0] = s[j][1] = s[j][2] = s[j][3] = 0.f; }
#pragma unroll
        for (int ks = 0; ks < 8; ++ks) {
            int k0 = ks * 8;
#pragma unroll
            for (int j = 0; j < 8; ++j) {
                unsigned bf[2];
                const float* kb = Ks + (ch * 64 + j * 8 + gid) * KSTR + k0;
                bf[0] = f2tf(kb[tig]);
                bf[1] = f2tf(kb[tig + 4]);
                mma8(s[j], qf[ks], bf);
            }
        }
#pragma unroll
        for (int j = 0; j < 8; ++j) {
            float p0 = __expf(s[j][0] - m[0]) * invz[0];
            float p1 = __expf(s[j][1] - m[0]) * invz[0];
            float p2 = __expf(s[j][2] - m[1]) * invz[1];
            float p3 = __expf(s[j][3] - m[1]) * invz[1];
            int cc = c * CK + ch * 64 + j * 8 + tig * 2;
            *(float2*)(series + srow + (size_t)gid * L_ + cc)       = make_float2(p0, p1);
            *(float2*)(series + srow + (size_t)(gid + 8) * L_ + cc) = make_float2(p2, p3);
            int lc = ch * 64 + j * 8 + tig * 2;
            *(float2*)(Ps + (mt + gid) * PST + lc)     = make_float2(p0, p1);
            *(float2*)(Ps + (mt + gid + 8) * PST + lc) = make_float2(p2, p3);
        }
        __syncthreads();

#pragma unroll 4
        for (int kk = 0; kk < 16; ++kk) {
            int kloc = kk * 8;
            unsigned af[4];
            af[0] = f2tf(Ps[(mt + gid) * PST + kloc + tig]);
            af[1] = f2tf(Ps[(mt + gid + 8) * PST + kloc + tig]);
            af[2] = f2tf(Ps[(mt + gid) * PST + kloc + tig + 4]);
            af[3] = f2tf(Ps[(mt + gid + 8) * PST + kloc + tig + 4]);
#pragma unroll
            for (int j = 0; j < 4; ++j) {
                int n0 = ch * 32 + j * 8;
                unsigned bf[2];
                bf[0] = f2tf(Vs[(kloc + tig) * VSTR + n0 + gid]);
                bf[1] = f2tf(Vs[(kloc + tig + 4) * VSTR + n0 + gid]);
                mma8(oa[j], af, bf);
            }
        }
    }

    // epilogue -> g_Op
#pragma unroll
    for (int j = 0; j < 4; ++j) {
        int dc = h * DK_ + ch * 32 + j * 8 + tig * 2;
        float* o0 = g_Op + (size_t)(b * L_ + row0 + mt + gid) * D_ + dc;
        *(float2*)o0 = make_float2(oa[j][0], oa[j][1]);
        float* o1 = g_Op + (size_t)(b * L_ + row0 + mt + gid + 8) * D_ + dc;
        *(float2*)o1 = make_float2(oa[j][2], oa[j][3]);
    }
}

// ---------------- launch ----------------
extern "C" void kernel_launch(void* const* d_in, const int* in_sizes, int n_in,
                              void* d_out, int out_size) {
    (void)in_sizes; (void)n_in; (void)out_size;
    const float* Sigma = (const float*)d_in[0];
    const float* Q     = (const float*)d_in[1];
    const float* K     = (const float*)d_in[2];
    const float* V     = (const float*)d_in[3];
    const float* Wsig  = (const float*)d_in[4];
    const float* Wq    = (const float*)d_in[5];
    const float* Wk    = (const float*)d_in[6];
    const float* Wv    = (const float*)d_in[7];
    const float* Wo    = (const float*)d_in[8];

    float* outp   = (float*)d_out;
    float* prior  = outp;
    float* series = outp + (size_t)HB_ * L_ * L_;
    float* fout   = series + (size_t)HB_ * L_ * L_;

    float *pQp, *pKp, *pVp, *pOp;
    cudaGetSymbolAddress((void**)&pQp, g_Qp);
    cudaGetSymbolAddress((void**)&pKp, g_Kp);
    cudaGetSymbolAddress((void**)&pVp, g_Vp);
    cudaGetSymbolAddress((void**)&pOp, g_Op);

    cudaFuncSetAttribute(gemm64,
                         cudaFuncAttributeMaxDynamicSharedMemorySize, GEMM_SMEM_BYTES);
    cudaFuncSetAttribute(attn2,
                         cudaFuncAttributeMaxDynamicSharedMemorySize, ATTN_SMEM);

    sigma_proj<<<(H_ * BL_ + 255) / 256, 256>>>(Sigma, Wsig);
    prior_kernel<<<H_ * BL_, 256>>>(prior);

    // fused QKV projections: grid.z selects the (A, W, C) triple
    gemm64<<<dim3(4, 64, 3), 256, GEMM_SMEM_BYTES>>>(Q, Wq, pQp, K, Wk, pKp, V, Wv, pVp);

    attn2<<<dim3(L_ / TMR, HB_), 256, ATTN_SMEM>>>(series);

    gemm64<<<dim3(4, 64, 1), 256, GEMM_SMEM_BYTES>>>(pOp, Wo, fout,
                                                     pOp, Wo, fout, pOp, Wo, fout);
}